// round 3
// baseline (speedup 1.0000x reference)
#include <cuda_runtime.h>
#include <math.h>
#include <stdint.h>

// ---------------- problem constants ----------------
#define B_    32
#define S_    512
#define D_    512
#define NROWS (B_ * S_)      // 16384
#define H_    4
#define HD_   128
#define DFF   2048
#define NQ    8
#define NL    4
#define QKVLD 1536

// ---------------- scratch (device globals; no cudaMalloc allowed) ----------------
__device__ float g_qkv [NROWS * 3 * D_];
__device__ float g_buf1[NROWS * DFF];        // scores/probs (32*4*512*512), later h
__device__ float g_vt  [B_ * H_ * HD_ * S_]; // V transposed per (b,h): [128][512]
__device__ float g_attn[NROWS * D_];
__device__ float g_proj[NROWS * D_];
__device__ float g_x1  [NROWS * D_];
__device__ float g_x2  [NROWS * D_];
__device__ float g_ffn [NROWS * D_];
__device__ float g_ang [NROWS * NQ];
__device__ float g_z   [NROWS * NQ];

// ---------------- cp.async helpers ----------------
__device__ __forceinline__ void cp16(uint32_t dst, const void* src) {
    asm volatile("cp.async.cg.shared.global [%0], [%1], 16;" :: "r"(dst), "l"(src));
}
__device__ __forceinline__ void cp_commit() {
    asm volatile("cp.async.commit_group;");
}
template<int N> __device__ __forceinline__ void cp_wait() {
    asm volatile("cp.async.wait_group %0;" :: "n"(N));
}
__device__ __forceinline__ uint32_t tf32_of(float f) {
    uint32_t u;
    asm("cvt.rna.tf32.f32 %0, %1;" : "=r"(u) : "f"(f));
    return u;
}
__device__ __forceinline__ void mma_tf32(float (&c)[4], const uint32_t (&a)[4], const uint32_t (&b)[2]) {
    asm volatile(
        "mma.sync.aligned.m16n8k8.row.col.f32.tf32.tf32.f32 "
        "{%0,%1,%2,%3}, {%4,%5,%6,%7}, {%8,%9}, {%0,%1,%2,%3};"
        : "+f"(c[0]), "+f"(c[1]), "+f"(c[2]), "+f"(c[3])
        : "r"(a[0]), "r"(a[1]), "r"(a[2]), "r"(a[3]), "r"(b[0]), "r"(b[1]));
}

// ---------------- unified TF32 tensor-core GEMM ----------------
// C[M,N] = alpha * A[M,K] * B[N,K]^T (+bias) (+gelu), row-major, batched by blockIdx.z=(b*4+h)
// Block tile 128x128, BK=16, 256 threads, 8 warps of 64x32.
// Both A and B tiles stored in smem as [row][k] with row stride 20 (conflict-free fragment LDS).
#define SSTR 20
template<int EPI>  // 0: *alpha ; 1: +bias ; 2: +bias then exact gelu
__global__ void __launch_bounds__(256)
gemm_tf32(const float* __restrict__ A, int lda, long long saB, long long saH,
          const float* __restrict__ B, int ldb, long long sbB, long long sbH,
          float* __restrict__ C, int ldc, long long scB, long long scH,
          int K, const float* __restrict__ bias, float alpha) {
    __shared__ float As[2][128 * SSTR];
    __shared__ float Bs[2][128 * SSTR];

    const int z = blockIdx.z, zb = z >> 2, zh = z & 3;
    const float* Ab = A + (long long)zb * saB + (long long)zh * saH + (size_t)blockIdx.y * 128 * lda;
    const float* Bb = B + (long long)zb * sbB + (long long)zh * sbH + (size_t)blockIdx.x * 128 * ldb;
    float* Cb = C + (long long)zb * scB + (long long)zh * scH;

    const int tid = threadIdx.x;
    const int lrow = tid >> 1;          // 0..127
    const int lq   = (tid & 1) * 8;     // 0 or 8
    const int lane = tid & 31, wid = tid >> 5;
    const int warp_m = wid & 1, warp_n = wid >> 1;
    const int mbase = warp_m * 64, nbase = warp_n * 32;
    const int gi = lane >> 2, ti = lane & 3;

    const uint32_t sA0 = (uint32_t)__cvta_generic_to_shared(&As[0][0]);
    const uint32_t sB0 = (uint32_t)__cvta_generic_to_shared(&Bs[0][0]);
    const uint32_t soff = (uint32_t)(lrow * SSTR + lq) * 4;
    const uint32_t bufstep = 128 * SSTR * 4;

    float acc[4][4][4] = {};

    const int KT = K / 16;
    // prologue
    {
        const float* ap = Ab + (size_t)lrow * lda + lq;
        const float* bp = Bb + (size_t)lrow * ldb + lq;
        cp16(sA0 + soff, ap);       cp16(sA0 + soff + 16, ap + 4);
        cp16(sB0 + soff, bp);       cp16(sB0 + soff + 16, bp + 4);
        cp_commit();
    }
    for (int kt = 0; kt < KT; kt++) {
        const int nxt = kt + 1;
        if (nxt < KT) {
            const int nb = nxt & 1;
            const float* ap = Ab + (size_t)lrow * lda + nxt * 16 + lq;
            const float* bp = Bb + (size_t)lrow * ldb + nxt * 16 + lq;
            cp16(sA0 + nb * bufstep + soff, ap);       cp16(sA0 + nb * bufstep + soff + 16, ap + 4);
            cp16(sB0 + nb * bufstep + soff, bp);       cp16(sB0 + nb * bufstep + soff + 16, bp + 4);
            cp_commit();
            cp_wait<1>();
        } else {
            cp_wait<0>();
        }
        __syncthreads();
        const float* as = As[kt & 1];
        const float* bs = Bs[kt & 1];
        #pragma unroll
        for (int hk = 0; hk < 2; hk++) {
            const int kk = hk * 8 + ti;
            uint32_t afr[4][4], bfr[4][2];
            #pragma unroll
            for (int mf = 0; mf < 4; mf++) {
                const float* ap = as + (mbase + mf * 16 + gi) * SSTR + kk;
                afr[mf][0] = tf32_of(ap[0]);
                afr[mf][1] = tf32_of(ap[8 * SSTR]);
                afr[mf][2] = tf32_of(ap[4]);
                afr[mf][3] = tf32_of(ap[8 * SSTR + 4]);
            }
            #pragma unroll
            for (int nf = 0; nf < 4; nf++) {
                const float* bp = bs + (nbase + nf * 8 + gi) * SSTR + kk;
                bfr[nf][0] = tf32_of(bp[0]);
                bfr[nf][1] = tf32_of(bp[4]);
            }
            #pragma unroll
            for (int mf = 0; mf < 4; mf++)
                #pragma unroll
                for (int nf = 0; nf < 4; nf++)
                    mma_tf32(acc[mf][nf], afr[mf], bfr[nf]);
        }
        __syncthreads();
    }

    // epilogue
    #pragma unroll
    for (int mf = 0; mf < 4; mf++) {
        const int row = blockIdx.y * 128 + mbase + mf * 16 + gi;
        #pragma unroll
        for (int nf = 0; nf < 4; nf++) {
            const int col = blockIdx.x * 128 + nbase + nf * 8 + ti * 2;
            float v0 = acc[mf][nf][0], v1 = acc[mf][nf][1];
            float v2 = acc[mf][nf][2], v3 = acc[mf][nf][3];
            if (EPI == 0) {
                v0 *= alpha; v1 *= alpha; v2 *= alpha; v3 *= alpha;
            } else {
                const float b0 = bias[col], b1 = bias[col + 1];
                v0 += b0; v1 += b1; v2 += b0; v3 += b1;
                if (EPI == 2) {
                    v0 = 0.5f * v0 * (1.0f + erff(v0 * 0.70710678118654752f));
                    v1 = 0.5f * v1 * (1.0f + erff(v1 * 0.70710678118654752f));
                    v2 = 0.5f * v2 * (1.0f + erff(v2 * 0.70710678118654752f));
                    v3 = 0.5f * v3 * (1.0f + erff(v3 * 0.70710678118654752f));
                }
            }
            *reinterpret_cast<float2*>(Cb + (size_t)row * ldc + col)       = make_float2(v0, v1);
            *reinterpret_cast<float2*>(Cb + (size_t)(row + 8) * ldc + col) = make_float2(v2, v3);
        }
    }
}

// ---------------- V transpose: vt[bh][n][s] = qkv.v[b][s][h][n] ----------------
__global__ void vtrans_k(const float* __restrict__ qkv, float* __restrict__ vt) {
    __shared__ float t[32][33];
    const int bh = blockIdx.z, b = bh >> 2, h = bh & 3;
    const int s0 = blockIdx.x * 32, n0 = blockIdx.y * 32;
    const float* src = qkv + (size_t)b * S_ * QKVLD + 2 * D_ + h * HD_;
    const int tx = threadIdx.x, ty = threadIdx.y;
    #pragma unroll
    for (int i = 0; i < 32; i += 8)
        t[ty + i][tx] = src[(size_t)(s0 + ty + i) * QKVLD + n0 + tx];
    __syncthreads();
    float* dst = vt + (size_t)bh * HD_ * S_;
    #pragma unroll
    for (int i = 0; i < 32; i += 8)
        dst[(size_t)(n0 + ty + i) * S_ + s0 + tx] = t[tx][ty + i];
}

// ---------------- reductions / norms ----------------
__device__ __forceinline__ float block_reduce_sum(float v, float* red) {
    const int t = threadIdx.x;
    red[t] = v;
    __syncthreads();
    for (int s = 128; s > 0; s >>= 1) {
        if (t < s) red[t] += red[t + s];
        __syncthreads();
    }
    float r = red[0];
    __syncthreads();
    return r;
}

__global__ void softmax_k(float* __restrict__ sc) {
    __shared__ float red[256];
    const size_t row = blockIdx.x;
    float* p = sc + row * 512;
    const int t = threadIdx.x;
    float v0 = p[t], v1 = p[t + 256];
    red[t] = fmaxf(v0, v1);
    __syncthreads();
    for (int s = 128; s > 0; s >>= 1) {
        if (t < s) red[t] = fmaxf(red[t], red[t + s]);
        __syncthreads();
    }
    float mx = red[0];
    __syncthreads();
    float e0 = expf(v0 - mx), e1 = expf(v1 - mx);
    float inv = 1.0f / block_reduce_sum(e0 + e1, red);
    p[t] = e0 * inv;
    p[t + 256] = e1 * inv;
}

__global__ void add_ln_k(const float* __restrict__ a, const float* __restrict__ b,
                         const float* __restrict__ g, const float* __restrict__ be,
                         float* __restrict__ out) {
    __shared__ float red[256];
    const size_t row = blockIdx.x;
    const int t = threadIdx.x;
    float v0 = a[row * 512 + t] + b[row * 512 + t];
    float v1 = a[row * 512 + t + 256] + b[row * 512 + t + 256];
    float mean = block_reduce_sum(v0 + v1, red) * (1.0f / 512.0f);
    float d0 = v0 - mean, d1 = v1 - mean;
    float rstd = rsqrtf(block_reduce_sum(d0 * d0 + d1 * d1, red) * (1.0f / 512.0f) + 1e-5f);
    out[row * 512 + t]       = d0 * rstd * g[t] + be[t];
    out[row * 512 + t + 256] = d1 * rstd * g[t + 256] + be[t + 256];
}

__global__ void ln3_qin_k(const float* __restrict__ x1, const float* __restrict__ g,
                          const float* __restrict__ be, const float* __restrict__ qw,
                          const float* __restrict__ qb, float* __restrict__ ang) {
    __shared__ float rowv[512];
    __shared__ float red[256];
    const size_t row = blockIdx.x;
    const float* p = x1 + row * 512;
    const int t = threadIdx.x;
    float v0 = p[t], v1 = p[t + 256];
    rowv[t] = v0;
    rowv[t + 256] = v1;
    float mean = block_reduce_sum(v0 + v1, red) * (1.0f / 512.0f);
    float d0 = v0 - mean, d1 = v1 - mean;
    float rstd = rsqrtf(block_reduce_sum(d0 * d0 + d1 * d1, red) * (1.0f / 512.0f) + 1e-5f);
    const int w = t >> 5, lane = t & 31;
    float dot = 0.0f;
    for (int k = lane; k < 512; k += 32) {
        float xn = (rowv[k] - mean) * rstd * g[k] + be[k];
        dot = fmaf(xn, qw[w * 512 + k], dot);
    }
    #pragma unroll
    for (int o = 16; o > 0; o >>= 1) dot += __shfl_xor_sync(0xffffffffu, dot, o);
    if (lane == 0) ang[row * 8 + w] = dot + qb[w];
}

// ---------------- 8-qubit statevector simulator (one warp per token) ----------------
__device__ __forceinline__ void rx_gate(float2* s, int pos, float c, float sn, int lane) {
    const int stride = 1 << pos;
    for (int p = lane; p < 128; p += 32) {
        int i0 = ((p >> pos) << (pos + 1)) | (p & (stride - 1));
        int i1 = i0 | stride;
        float2 a = s[i0], b = s[i1];
        s[i0] = make_float2(c * a.x + sn * b.y, c * a.y - sn * b.x);
        s[i1] = make_float2(sn * a.y + c * b.x, -sn * a.x + c * b.y);
    }
}
__device__ __forceinline__ void rz_gate(float2* s, int pos, float c, float sn, int lane) {
    for (int i = lane; i < 256; i += 32) {
        float2 a = s[i];
        if (i & (1 << pos)) s[i] = make_float2(a.x * c - a.y * sn, a.y * c + a.x * sn);
        else                s[i] = make_float2(a.x * c + a.y * sn, a.y * c - a.x * sn);
    }
}
__device__ __forceinline__ void cnot_gate(float2* s, int pt, int lane) {
    for (int p = lane; p < 64; p += 32) {
        int lower = p & ((1 << pt) - 1);
        int upper = p >> pt;
        int base = (upper << (pt + 2)) | lower;
        int i2 = base | (2 << pt);
        int i3 = base | (3 << pt);
        float2 tmp = s[i2];
        s[i2] = s[i3];
        s[i3] = tmp;
    }
}
__global__ void quantum_k(const float* __restrict__ angles, const float* __restrict__ qw,
                          float* __restrict__ zout) {
    __shared__ float2 st[8][256];
    const int warp = threadIdx.x >> 5, lane = threadIdx.x & 31;
    const size_t row = (size_t)blockIdx.x * 8 + warp;
    float2* s = st[warp];
    for (int i = lane; i < 256; i += 32) s[i] = make_float2(0.0f, 0.0f);
    __syncwarp();
    if (lane == 0) s[0] = make_float2(1.0f, 0.0f);
    __syncwarp();
    for (int q = 0; q < 8; q++) {
        float th = 0.5f * angles[row * 8 + q];
        float sn, c;
        sincosf(th, &sn, &c);
        rx_gate(s, 7 - q, c, sn, lane);
        __syncwarp();
        rz_gate(s, 7 - q, c, sn, lane);
        __syncwarp();
    }
    for (int l = 0; l < NL; l++) {
        for (int q = 0; q < 8; q++) {
            float snx, cx;
            sincosf(0.5f * qw[l * 16 + q], &snx, &cx);
            rx_gate(s, 7 - q, cx, snx, lane);
            __syncwarp();
            float snz, cz;
            sincosf(0.5f * qw[l * 16 + 8 + q], &snz, &cz);
            rz_gate(s, 7 - q, cz, snz, lane);
            __syncwarp();
        }
        for (int ctrl = 0; ctrl < 7; ctrl++) {
            cnot_gate(s, 6 - ctrl, lane);
            __syncwarp();
        }
    }
    float acc[8] = {0, 0, 0, 0, 0, 0, 0, 0};
    for (int i = lane; i < 256; i += 32) {
        float2 a = s[i];
        float pr = a.x * a.x + a.y * a.y;
        #pragma unroll
        for (int q = 0; q < 8; q++)
            acc[q] += (i & (1 << (7 - q))) ? -pr : pr;
    }
    #pragma unroll
    for (int q = 0; q < 8; q++)
        #pragma unroll
        for (int o = 16; o > 0; o >>= 1)
            acc[q] += __shfl_xor_sync(0xffffffffu, acc[q], o);
    if (lane == 0) {
        #pragma unroll
        for (int q = 0; q < 8; q++) zout[row * 8 + q] = acc[q];
    }
}

__global__ void qout_resid_k(const float* __restrict__ x1, const float* __restrict__ z,
                             const float* __restrict__ w, const float* __restrict__ bias,
                             float* __restrict__ x2) {
    __shared__ float zs[8];
    const size_t row = blockIdx.x;
    if (threadIdx.x < 8) zs[threadIdx.x] = z[row * 8 + threadIdx.x];
    __syncthreads();
    for (int j = threadIdx.x; j < 512; j += 256) {
        const float* wj = w + j * 8;
        float acc = bias[j];
        #pragma unroll
        for (int q = 0; q < 8; q++) acc = fmaf(zs[q], wj[q], acc);
        x2[row * 512 + j] = x1[row * 512 + j] + acc;
    }
}

// ---------------- launch ----------------
extern "C" void kernel_launch(void* const* d_in, const int* in_sizes, int n_in,
                              void* d_out, int out_size) {
    const float* x          = (const float*)d_in[0];
    const float* attn_in_w  = (const float*)d_in[1];
    const float* attn_in_b  = (const float*)d_in[2];
    const float* attn_out_w = (const float*)d_in[3];
    const float* attn_out_b = (const float*)d_in[4];
    const float* ln1_g      = (const float*)d_in[5];
    const float* ln1_b      = (const float*)d_in[6];
    const float* ln2_g      = (const float*)d_in[7];
    const float* ln2_b      = (const float*)d_in[8];
    const float* ln3_g      = (const float*)d_in[9];
    const float* ln3_b      = (const float*)d_in[10];
    const float* qin_w      = (const float*)d_in[11];
    const float* qin_b      = (const float*)d_in[12];
    const float* qweights   = (const float*)d_in[13];
    const float* qout_w     = (const float*)d_in[14];
    const float* qout_b     = (const float*)d_in[15];
    const float* ffn_w1     = (const float*)d_in[16];
    const float* ffn_b1     = (const float*)d_in[17];
    const float* ffn_w2     = (const float*)d_in[18];
    const float* ffn_b2     = (const float*)d_in[19];
    float* out = (float*)d_out;

    float *qkv, *buf1, *vt, *attn, *proj, *x1, *x2, *ffn, *ang, *z;
    cudaGetSymbolAddress((void**)&qkv,  g_qkv);
    cudaGetSymbolAddress((void**)&buf1, g_buf1);
    cudaGetSymbolAddress((void**)&vt,   g_vt);
    cudaGetSymbolAddress((void**)&attn, g_attn);
    cudaGetSymbolAddress((void**)&proj, g_proj);
    cudaGetSymbolAddress((void**)&x1,   g_x1);
    cudaGetSymbolAddress((void**)&x2,   g_x2);
    cudaGetSymbolAddress((void**)&ffn,  g_ffn);
    cudaGetSymbolAddress((void**)&ang,  g_ang);
    cudaGetSymbolAddress((void**)&z,    g_z);

    const dim3 blk(256);
    const long long SS = (long long)S_ * S_;

    // QKV projection: (16384 x 512) @ (1536 x 512)^T + bias
    gemm_tf32<1><<<dim3(QKVLD / 128, NROWS / 128, 1), blk>>>(
        x, D_, 0, 0, attn_in_w, D_, 0, 0, qkv, QKVLD, 0, 0, D_, attn_in_b, 1.0f);
    // scores = Q K^T / sqrt(hd), batched over 128 (b,h)
    gemm_tf32<0><<<dim3(4, 4, B_ * H_), blk>>>(
        qkv, QKVLD, (long long)S_ * QKVLD, HD_,
        qkv + D_, QKVLD, (long long)S_ * QKVLD, HD_,
        buf1, S_, 4 * SS, SS, HD_, nullptr, 0.08838834764831845f);
    softmax_k<<<B_ * H_ * S_, blk>>>(buf1);
    // transpose V
    vtrans_k<<<dim3(S_ / 32, HD_ / 32, B_ * H_), dim3(32, 8)>>>(qkv, vt);
    // o = P V  (N=128 per head)
    gemm_tf32<0><<<dim3(1, 4, B_ * H_), blk>>>(
        buf1, S_, 4 * SS, SS,
        vt, S_, (long long)H_ * HD_ * S_, (long long)HD_ * S_,
        attn, D_, (long long)S_ * D_, HD_, S_, nullptr, 1.0f);
    // out projection
    gemm_tf32<1><<<dim3(D_ / 128, NROWS / 128, 1), blk>>>(
        attn, D_, 0, 0, attn_out_w, D_, 0, 0, proj, D_, 0, 0, D_, attn_out_b, 1.0f);
    // x1 = LN1(x + proj)
    add_ln_k<<<NROWS, blk>>>(x, proj, ln1_g, ln1_b, x1);
    // angles = LN3(x1) @ qin_w^T + qin_b
    ln3_qin_k<<<NROWS, blk>>>(x1, ln3_g, ln3_b, qin_w, qin_b, ang);
    // quantum expectation values
    quantum_k<<<NROWS / 8, blk>>>(ang, qweights, z);
    // x2 = x1 + z @ qout_w^T + qout_b
    qout_resid_k<<<NROWS, blk>>>(x1, z, qout_w, qout_b, x2);
    // FFN
    gemm_tf32<2><<<dim3(DFF / 128, NROWS / 128, 1), blk>>>(
        x2, D_, 0, 0, ffn_w1, D_, 0, 0, buf1, DFF, 0, 0, D_, ffn_b1, 1.0f);
    gemm_tf32<1><<<dim3(D_ / 128, NROWS / 128, 1), blk>>>(
        buf1, DFF, 0, 0, ffn_w2, DFF, 0, 0, ffn, D_, 0, 0, DFF, ffn_b2, 1.0f);
    // out = LN2(x2 + ffn)
    add_ln_k<<<NROWS, blk>>>(x2, ffn, ln2_g, ln2_b, out);
}

// round 4
// speedup vs baseline: 1.3695x; 1.3695x over previous
#include <cuda_runtime.h>
#include <cuda_fp16.h>
#include <math.h>
#include <stdint.h>

// ---------------- problem constants ----------------
#define B_    32
#define S_    512
#define D_    512
#define NROWS (B_ * S_)      // 16384
#define H_    4
#define HD_   128
#define DFF   2048
#define NQ    8
#define NL    4
#define QKVLD 1536

// ---------------- scratch (device globals; no cudaMalloc allowed) ----------------
__device__ __half g_xh  [NROWS * D_];
__device__ __half g_wih [3 * D_ * D_];        // attn_in_w fp16
__device__ __half g_woh [D_ * D_];            // attn_out_w fp16
__device__ __half g_w1h [DFF * D_];           // ffn_w1 fp16
__device__ __half g_w2h [D_ * DFF];           // ffn_w2 fp16
__device__ __half g_qkvh[NROWS * 3 * D_];
__device__ float  g_buf1[NROWS * DFF];        // fp32 scores
__device__ __half g_hbuf[NROWS * DFF];        // fp16 probs, later fp16 h
__device__ __half g_vth [B_ * H_ * HD_ * S_];
__device__ __half g_attnh[NROWS * D_];
__device__ float  g_proj[NROWS * D_];
__device__ float  g_x1  [NROWS * D_];
__device__ float  g_x2  [NROWS * D_];
__device__ __half g_x2h [NROWS * D_];
__device__ float  g_ffn [NROWS * D_];
__device__ float  g_ang [NROWS * NQ];
__device__ float  g_z   [NROWS * NQ];

// ---------------- asm helpers ----------------
__device__ __forceinline__ void cp16(uint32_t dst, const void* src) {
    asm volatile("cp.async.cg.shared.global [%0], [%1], 16;" :: "r"(dst), "l"(src));
}
__device__ __forceinline__ void cp_commit() { asm volatile("cp.async.commit_group;"); }
template<int N> __device__ __forceinline__ void cp_wait() {
    asm volatile("cp.async.wait_group %0;" :: "n"(N));
}
__device__ __forceinline__ void ldm_x4(uint32_t (&r)[4], uint32_t addr) {
    asm volatile("ldmatrix.sync.aligned.m8n8.x4.shared.b16 {%0,%1,%2,%3}, [%4];"
                 : "=r"(r[0]), "=r"(r[1]), "=r"(r[2]), "=r"(r[3]) : "r"(addr));
}
__device__ __forceinline__ void mma_f16(float (&c)[4], const uint32_t (&a)[4],
                                        uint32_t b0, uint32_t b1) {
    asm volatile(
        "mma.sync.aligned.m16n8k16.row.col.f32.f16.f16.f32 "
        "{%0,%1,%2,%3}, {%4,%5,%6,%7}, {%8,%9}, {%0,%1,%2,%3};"
        : "+f"(c[0]), "+f"(c[1]), "+f"(c[2]), "+f"(c[3])
        : "r"(a[0]), "r"(a[1]), "r"(a[2]), "r"(a[3]), "r"(b0), "r"(b1));
}

// ---------------- unified FP16 tensor-core GEMM ----------------
// C[M,N] = alpha * A[M,K](fp16,row) * B[N,K](fp16,row)^T (+bias)(+gelu)
// batched by blockIdx.z = b*4+h via element strides. Block tile 128x128, BK=32,
// 256 threads = 8 warps of 64x32. smem rows padded to 40 halves (conflict-free ldmatrix).
#define SH 40
template<int EPI, int HOUT>  // EPI 0:*alpha 1:+bias 2:+bias,gelu ; HOUT 0:f32 out 1:f16 out
__global__ void __launch_bounds__(256)
gemm_h16(const __half* __restrict__ A, int lda, long long saB, long long saH,
         const __half* __restrict__ B, int ldb, long long sbB, long long sbH,
         void* __restrict__ Cv, int ldc, long long scB, long long scH,
         int K, const float* __restrict__ bias, float alpha) {
    __shared__ __half As[2][128 * SH];
    __shared__ __half Bs[2][128 * SH];

    const int z = blockIdx.z, zb = z >> 2, zh = z & 3;
    const __half* Ab = A + (long long)zb * saB + (long long)zh * saH + (size_t)blockIdx.y * 128 * lda;
    const __half* Bb = B + (long long)zb * sbB + (long long)zh * sbH + (size_t)blockIdx.x * 128 * ldb;

    const int tid = threadIdx.x;
    const int lane = tid & 31, wid = tid >> 5;
    const int warp_m = wid & 1, warp_n = wid >> 1;
    const int mbase = warp_m * 64, nbase = warp_n * 32;

    // cp.async coords: thread -> (row, 2 consecutive 16B chunks)
    const int crow = tid >> 1;
    const int coff = (tid & 1) * 16;            // half index within 32-wide row
    const uint32_t sA = (uint32_t)__cvta_generic_to_shared(&As[0][0]);
    const uint32_t sB = (uint32_t)__cvta_generic_to_shared(&Bs[0][0]);
    const uint32_t cdst = (uint32_t)(crow * SH + coff) * 2;
    const uint32_t bstep = 128 * SH * 2;

    // ldmatrix fragment rows/cols
    const int arow = mbase + (lane & 7) + 8 * ((lane >> 3) & 1);
    const int acol = 8 * ((lane >> 4) & 1);
    const int brow = nbase + (lane & 7) + 8 * ((lane >> 4) & 1);
    const int bcol = 8 * ((lane >> 3) & 1);

    float acc[4][4][4] = {};
    const int KT = K / 32;

    {
        const __half* ap = Ab + (size_t)crow * lda + coff;
        const __half* bp = Bb + (size_t)crow * ldb + coff;
        cp16(sA + cdst, ap); cp16(sA + cdst + 16, ap + 8);
        cp16(sB + cdst, bp); cp16(sB + cdst + 16, bp + 8);
        cp_commit();
    }
    for (int kt = 0; kt < KT; kt++) {
        if (kt + 1 < KT) {
            const int nb = (kt + 1) & 1;
            const __half* ap = Ab + (size_t)crow * lda + (kt + 1) * 32 + coff;
            const __half* bp = Bb + (size_t)crow * ldb + (kt + 1) * 32 + coff;
            cp16(sA + nb * bstep + cdst, ap); cp16(sA + nb * bstep + cdst + 16, ap + 8);
            cp16(sB + nb * bstep + cdst, bp); cp16(sB + nb * bstep + cdst + 16, bp + 8);
            cp_commit();
            cp_wait<1>();
        } else {
            cp_wait<0>();
        }
        __syncthreads();
        const uint32_t aB = sA + (kt & 1) * bstep;
        const uint32_t bB = sB + (kt & 1) * bstep;
        #pragma unroll
        for (int hk = 0; hk < 2; hk++) {
            const int kb = hk * 16;
            uint32_t afr[4][4];
            #pragma unroll
            for (int mf = 0; mf < 4; mf++)
                ldm_x4(afr[mf], aB + (uint32_t)((arow + mf * 16) * SH + kb + acol) * 2);
            uint32_t bfr[2][4];
            #pragma unroll
            for (int n2 = 0; n2 < 2; n2++)
                ldm_x4(bfr[n2], bB + (uint32_t)((brow + n2 * 16) * SH + kb + bcol) * 2);
            #pragma unroll
            for (int mf = 0; mf < 4; mf++) {
                mma_f16(acc[mf][0], afr[mf], bfr[0][0], bfr[0][1]);
                mma_f16(acc[mf][1], afr[mf], bfr[0][2], bfr[0][3]);
                mma_f16(acc[mf][2], afr[mf], bfr[1][0], bfr[1][1]);
                mma_f16(acc[mf][3], afr[mf], bfr[1][2], bfr[1][3]);
            }
        }
        __syncthreads();
    }

    // epilogue
    const int gi = lane >> 2, ti = lane & 3;
    float* Cf = (float*)Cv + (long long)zb * scB + (long long)zh * scH;
    __half* Ch = (__half*)Cv + (long long)zb * scB + (long long)zh * scH;
    #pragma unroll
    for (int mf = 0; mf < 4; mf++) {
        const int row = blockIdx.y * 128 + mbase + mf * 16 + gi;
        #pragma unroll
        for (int nf = 0; nf < 4; nf++) {
            const int col = blockIdx.x * 128 + nbase + nf * 8 + ti * 2;
            float v0 = acc[mf][nf][0], v1 = acc[mf][nf][1];
            float v2 = acc[mf][nf][2], v3 = acc[mf][nf][3];
            if (EPI == 0) {
                v0 *= alpha; v1 *= alpha; v2 *= alpha; v3 *= alpha;
            } else {
                const float b0 = bias[col], b1 = bias[col + 1];
                v0 += b0; v1 += b1; v2 += b0; v3 += b1;
                if (EPI == 2) {
                    v0 = 0.5f * v0 * (1.0f + erff(v0 * 0.70710678118654752f));
                    v1 = 0.5f * v1 * (1.0f + erff(v1 * 0.70710678118654752f));
                    v2 = 0.5f * v2 * (1.0f + erff(v2 * 0.70710678118654752f));
                    v3 = 0.5f * v3 * (1.0f + erff(v3 * 0.70710678118654752f));
                }
            }
            if (HOUT) {
                *reinterpret_cast<__half2*>(Ch + (size_t)row * ldc + col) =
                    __floats2half2_rn(v0, v1);
                *reinterpret_cast<__half2*>(Ch + (size_t)(row + 8) * ldc + col) =
                    __floats2half2_rn(v2, v3);
            } else {
                *reinterpret_cast<float2*>(Cf + (size_t)row * ldc + col) = make_float2(v0, v1);
                *reinterpret_cast<float2*>(Cf + (size_t)(row + 8) * ldc + col) = make_float2(v2, v3);
            }
        }
    }
}

// ---------------- fp32 -> fp16 conversion ----------------
__global__ void f2h_k(const float* __restrict__ in, __half* __restrict__ out, int n4) {
    int i = blockIdx.x * blockDim.x + threadIdx.x;
    if (i < n4) {
        float4 v = reinterpret_cast<const float4*>(in)[i];
        __half2 h0 = __floats2half2_rn(v.x, v.y);
        __half2 h1 = __floats2half2_rn(v.z, v.w);
        reinterpret_cast<__half2*>(out)[i * 2]     = h0;
        reinterpret_cast<__half2*>(out)[i * 2 + 1] = h1;
    }
}

// ---------------- V transpose (fp16): vt[bh][n][s] = qkvh.v[b][s][h][n] ----------------
__global__ void vtrans_h(const __half* __restrict__ qkv, __half* __restrict__ vt) {
    __shared__ __half t[32][33];
    const int bh = blockIdx.z, b = bh >> 2, h = bh & 3;
    const int s0 = blockIdx.x * 32, n0 = blockIdx.y * 32;
    const __half* src = qkv + (size_t)b * S_ * QKVLD + 2 * D_ + h * HD_;
    const int tx = threadIdx.x, ty = threadIdx.y;
    #pragma unroll
    for (int i = 0; i < 32; i += 8)
        t[ty + i][tx] = src[(size_t)(s0 + ty + i) * QKVLD + n0 + tx];
    __syncthreads();
    __half* dst = vt + (size_t)bh * HD_ * S_;
    #pragma unroll
    for (int i = 0; i < 32; i += 8)
        dst[(size_t)(n0 + ty + i) * S_ + s0 + tx] = t[tx][ty + i];
}

// ---------------- reductions / norms ----------------
__device__ __forceinline__ float block_reduce_sum(float v, float* red) {
    const int t = threadIdx.x;
    red[t] = v;
    __syncthreads();
    for (int s = 128; s > 0; s >>= 1) {
        if (t < s) red[t] += red[t + s];
        __syncthreads();
    }
    float r = red[0];
    __syncthreads();
    return r;
}

// softmax: fp32 scores in, fp16 probs out
__global__ void softmax_h(const float* __restrict__ sc, __half* __restrict__ pr) {
    __shared__ float red[256];
    const size_t row = blockIdx.x;
    const float* p = sc + row * 512;
    const int t = threadIdx.x;
    float v0 = p[t], v1 = p[t + 256];
    red[t] = fmaxf(v0, v1);
    __syncthreads();
    for (int s = 128; s > 0; s >>= 1) {
        if (t < s) red[t] = fmaxf(red[t], red[t + s]);
        __syncthreads();
    }
    float mx = red[0];
    __syncthreads();
    float e0 = expf(v0 - mx), e1 = expf(v1 - mx);
    float inv = 1.0f / block_reduce_sum(e0 + e1, red);
    pr[row * 512 + t]       = __float2half_rn(e0 * inv);
    pr[row * 512 + t + 256] = __float2half_rn(e1 * inv);
}

__global__ void add_ln_k(const float* __restrict__ a, const float* __restrict__ b,
                         const float* __restrict__ g, const float* __restrict__ be,
                         float* __restrict__ out) {
    __shared__ float red[256];
    const size_t row = blockIdx.x;
    const int t = threadIdx.x;
    float v0 = a[row * 512 + t] + b[row * 512 + t];
    float v1 = a[row * 512 + t + 256] + b[row * 512 + t + 256];
    float mean = block_reduce_sum(v0 + v1, red) * (1.0f / 512.0f);
    float d0 = v0 - mean, d1 = v1 - mean;
    float rstd = rsqrtf(block_reduce_sum(d0 * d0 + d1 * d1, red) * (1.0f / 512.0f) + 1e-5f);
    out[row * 512 + t]       = d0 * rstd * g[t] + be[t];
    out[row * 512 + t + 256] = d1 * rstd * g[t + 256] + be[t + 256];
}

__global__ void ln3_qin_k(const float* __restrict__ x1, const float* __restrict__ g,
                          const float* __restrict__ be, const float* __restrict__ qw,
                          const float* __restrict__ qb, float* __restrict__ ang) {
    __shared__ float rowv[512];
    __shared__ float red[256];
    const size_t row = blockIdx.x;
    const float* p = x1 + row * 512;
    const int t = threadIdx.x;
    float v0 = p[t], v1 = p[t + 256];
    rowv[t] = v0;
    rowv[t + 256] = v1;
    float mean = block_reduce_sum(v0 + v1, red) * (1.0f / 512.0f);
    float d0 = v0 - mean, d1 = v1 - mean;
    float rstd = rsqrtf(block_reduce_sum(d0 * d0 + d1 * d1, red) * (1.0f / 512.0f) + 1e-5f);
    const int w = t >> 5, lane = t & 31;
    float dot = 0.0f;
    for (int k = lane; k < 512; k += 32) {
        float xn = (rowv[k] - mean) * rstd * g[k] + be[k];
        dot = fmaf(xn, qw[w * 512 + k], dot);
    }
    #pragma unroll
    for (int o = 16; o > 0; o >>= 1) dot += __shfl_xor_sync(0xffffffffu, dot, o);
    if (lane == 0) ang[row * 8 + w] = dot + qb[w];
}

// ---------------- 8-qubit statevector simulator (one warp per token) ----------------
__device__ __forceinline__ void rx_gate(float2* s, int pos, float c, float sn, int lane) {
    const int stride = 1 << pos;
    for (int p = lane; p < 128; p += 32) {
        int i0 = ((p >> pos) << (pos + 1)) | (p & (stride - 1));
        int i1 = i0 | stride;
        float2 a = s[i0], b = s[i1];
        s[i0] = make_float2(c * a.x + sn * b.y, c * a.y - sn * b.x);
        s[i1] = make_float2(sn * a.y + c * b.x, -sn * a.x + c * b.y);
    }
}
__device__ __forceinline__ void rz_gate(float2* s, int pos, float c, float sn, int lane) {
    for (int i = lane; i < 256; i += 32) {
        float2 a = s[i];
        if (i & (1 << pos)) s[i] = make_float2(a.x * c - a.y * sn, a.y * c + a.x * sn);
        else                s[i] = make_float2(a.x * c + a.y * sn, a.y * c - a.x * sn);
    }
}
__device__ __forceinline__ void cnot_gate(float2* s, int pt, int lane) {
    for (int p = lane; p < 64; p += 32) {
        int lower = p & ((1 << pt) - 1);
        int upper = p >> pt;
        int base = (upper << (pt + 2)) | lower;
        int i2 = base | (2 << pt);
        int i3 = base | (3 << pt);
        float2 tmp = s[i2];
        s[i2] = s[i3];
        s[i3] = tmp;
    }
}
__global__ void quantum_k(const float* __restrict__ angles, const float* __restrict__ qw,
                          float* __restrict__ zout) {
    __shared__ float2 st[8][256];
    const int warp = threadIdx.x >> 5, lane = threadIdx.x & 31;
    const size_t row = (size_t)blockIdx.x * 8 + warp;
    float2* s = st[warp];
    for (int i = lane; i < 256; i += 32) s[i] = make_float2(0.0f, 0.0f);
    __syncwarp();
    if (lane == 0) s[0] = make_float2(1.0f, 0.0f);
    __syncwarp();
    for (int q = 0; q < 8; q++) {
        float th = 0.5f * angles[row * 8 + q];
        float sn, c;
        sincosf(th, &sn, &c);
        rx_gate(s, 7 - q, c, sn, lane);
        __syncwarp();
        rz_gate(s, 7 - q, c, sn, lane);
        __syncwarp();
    }
    for (int l = 0; l < NL; l++) {
        for (int q = 0; q < 8; q++) {
            float snx, cx;
            sincosf(0.5f * qw[l * 16 + q], &snx, &cx);
            rx_gate(s, 7 - q, cx, snx, lane);
            __syncwarp();
            float snz, cz;
            sincosf(0.5f * qw[l * 16 + 8 + q], &snz, &cz);
            rz_gate(s, 7 - q, cz, snz, lane);
            __syncwarp();
        }
        for (int ctrl = 0; ctrl < 7; ctrl++) {
            cnot_gate(s, 6 - ctrl, lane);
            __syncwarp();
        }
    }
    float acc[8] = {0, 0, 0, 0, 0, 0, 0, 0};
    for (int i = lane; i < 256; i += 32) {
        float2 a = s[i];
        float pr = a.x * a.x + a.y * a.y;
        #pragma unroll
        for (int q = 0; q < 8; q++)
            acc[q] += (i & (1 << (7 - q))) ? -pr : pr;
    }
    #pragma unroll
    for (int q = 0; q < 8; q++)
        #pragma unroll
        for (int o = 16; o > 0; o >>= 1)
            acc[q] += __shfl_xor_sync(0xffffffffu, acc[q], o);
    if (lane == 0) {
        #pragma unroll
        for (int q = 0; q < 8; q++) zout[row * 8 + q] = acc[q];
    }
}

// x2 = x1 + z @ qout_w^T + qout_b  (fp32 + fp16 copies)
__global__ void qout_resid_h(const float* __restrict__ x1, const float* __restrict__ z,
                             const float* __restrict__ w, const float* __restrict__ bias,
                             float* __restrict__ x2, __half* __restrict__ x2h) {
    __shared__ float zs[8];
    const size_t row = blockIdx.x;
    if (threadIdx.x < 8) zs[threadIdx.x] = z[row * 8 + threadIdx.x];
    __syncthreads();
    for (int j = threadIdx.x; j < 512; j += 256) {
        const float* wj = w + j * 8;
        float acc = bias[j];
        #pragma unroll
        for (int q = 0; q < 8; q++) acc = fmaf(zs[q], wj[q], acc);
        float v = x1[row * 512 + j] + acc;
        x2[row * 512 + j] = v;
        x2h[row * 512 + j] = __float2half_rn(v);
    }
}

// ---------------- launch ----------------
extern "C" void kernel_launch(void* const* d_in, const int* in_sizes, int n_in,
                              void* d_out, int out_size) {
    const float* x          = (const float*)d_in[0];
    const float* attn_in_w  = (const float*)d_in[1];
    const float* attn_in_b  = (const float*)d_in[2];
    const float* attn_out_w = (const float*)d_in[3];
    const float* attn_out_b = (const float*)d_in[4];
    const float* ln1_g      = (const float*)d_in[5];
    const float* ln1_b      = (const float*)d_in[6];
    const float* ln2_g      = (const float*)d_in[7];
    const float* ln2_b      = (const float*)d_in[8];
    const float* ln3_g      = (const float*)d_in[9];
    const float* ln3_b      = (const float*)d_in[10];
    const float* qin_w      = (const float*)d_in[11];
    const float* qin_b      = (const float*)d_in[12];
    const float* qweights   = (const float*)d_in[13];
    const float* qout_w     = (const float*)d_in[14];
    const float* qout_b     = (const float*)d_in[15];
    const float* ffn_w1     = (const float*)d_in[16];
    const float* ffn_b1     = (const float*)d_in[17];
    const float* ffn_w2     = (const float*)d_in[18];
    const float* ffn_b2     = (const float*)d_in[19];
    float* out = (float*)d_out;

    __half *xh, *wih, *woh, *w1h, *w2h, *qkvh, *hbuf, *vth, *attnh, *x2h;
    float *buf1, *proj, *x1, *x2, *ffn, *ang, *z;
    cudaGetSymbolAddress((void**)&xh,    g_xh);
    cudaGetSymbolAddress((void**)&wih,   g_wih);
    cudaGetSymbolAddress((void**)&woh,   g_woh);
    cudaGetSymbolAddress((void**)&w1h,   g_w1h);
    cudaGetSymbolAddress((void**)&w2h,   g_w2h);
    cudaGetSymbolAddress((void**)&qkvh,  g_qkvh);
    cudaGetSymbolAddress((void**)&buf1,  g_buf1);
    cudaGetSymbolAddress((void**)&hbuf,  g_hbuf);
    cudaGetSymbolAddress((void**)&vth,   g_vth);
    cudaGetSymbolAddress((void**)&attnh, g_attnh);
    cudaGetSymbolAddress((void**)&x2h,   g_x2h);
    cudaGetSymbolAddress((void**)&proj,  g_proj);
    cudaGetSymbolAddress((void**)&x1,    g_x1);
    cudaGetSymbolAddress((void**)&x2,    g_x2);
    cudaGetSymbolAddress((void**)&ffn,   g_ffn);
    cudaGetSymbolAddress((void**)&ang,   g_ang);
    cudaGetSymbolAddress((void**)&z,     g_z);

    const dim3 blk(256);
    const long long SS = (long long)S_ * S_;

    // fp32 -> fp16 conversions (input + weights)
    f2h_k<<<(NROWS * D_ / 4 + 255) / 256, blk>>>(x, xh, NROWS * D_ / 4);
    f2h_k<<<(3 * D_ * D_ / 4 + 255) / 256, blk>>>(attn_in_w, wih, 3 * D_ * D_ / 4);
    f2h_k<<<(D_ * D_ / 4 + 255) / 256, blk>>>(attn_out_w, woh, D_ * D_ / 4);
    f2h_k<<<(DFF * D_ / 4 + 255) / 256, blk>>>(ffn_w1, w1h, DFF * D_ / 4);
    f2h_k<<<(D_ * DFF / 4 + 255) / 256, blk>>>(ffn_w2, w2h, D_ * DFF / 4);

    // QKV projection -> fp16 qkv
    gemm_h16<1, 1><<<dim3(QKVLD / 128, NROWS / 128, 1), blk>>>(
        xh, D_, 0, 0, wih, D_, 0, 0, qkvh, QKVLD, 0, 0, D_, attn_in_b, 1.0f);
    // scores (fp32) = Q K^T / sqrt(hd), batched over 128 (b,h)
    gemm_h16<0, 0><<<dim3(4, 4, B_ * H_), blk>>>(
        qkvh, QKVLD, (long long)S_ * QKVLD, HD_,
        qkvh + D_, QKVLD, (long long)S_ * QKVLD, HD_,
        buf1, S_, 4 * SS, SS, HD_, nullptr, 0.08838834764831845f);
    // softmax -> fp16 probs
    softmax_h<<<B_ * H_ * S_, blk>>>(buf1, hbuf);
    // transpose V (fp16)
    vtrans_h<<<dim3(S_ / 32, HD_ / 32, B_ * H_), dim3(32, 8)>>>(qkvh, vth);
    // context = P V -> fp16
    gemm_h16<0, 1><<<dim3(1, 4, B_ * H_), blk>>>(
        hbuf, S_, 4 * SS, SS,
        vth, S_, (long long)H_ * HD_ * S_, (long long)HD_ * S_,
        attnh, D_, (long long)S_ * D_, HD_, S_, nullptr, 1.0f);
    // out projection -> fp32
    gemm_h16<1, 0><<<dim3(D_ / 128, NROWS / 128, 1), blk>>>(
        attnh, D_, 0, 0, woh, D_, 0, 0, proj, D_, 0, 0, D_, attn_out_b, 1.0f);
    // x1 = LN1(x + proj)
    add_ln_k<<<NROWS, blk>>>(x, proj, ln1_g, ln1_b, x1);
    // angles = LN3(x1) @ qin_w^T + qin_b
    ln3_qin_k<<<NROWS, blk>>>(x1, ln3_g, ln3_b, qin_w, qin_b, ang);
    // quantum expectation values
    quantum_k<<<NROWS / 8, blk>>>(ang, qweights, z);
    // x2 = x1 + z @ qout_w^T + qout_b (fp32 + fp16)
    qout_resid_h<<<NROWS, blk>>>(x1, z, qout_w, qout_b, x2, x2h);
    // FFN1: h = gelu(x2 @ w1^T + b1) -> fp16 (reuse hbuf)
    gemm_h16<2, 1><<<dim3(DFF / 128, NROWS / 128, 1), blk>>>(
        x2h, D_, 0, 0, w1h, D_, 0, 0, hbuf, DFF, 0, 0, D_, ffn_b1, 1.0f);
    // FFN2 -> fp32
    gemm_h16<1, 0><<<dim3(D_ / 128, NROWS / 128, 1), blk>>>(
        hbuf, DFF, 0, 0, w2h, DFF, 0, 0, ffn, D_, 0, 0, DFF, ffn_b2, 1.0f);
    // out = LN2(x2 + ffn)
    add_ln_k<<<NROWS, blk>>>(x2, ffn, ln2_g, ln2_b, out);
}

// round 6
// speedup vs baseline: 1.3984x; 1.0211x over previous
#include <cuda_runtime.h>
#include <cuda_fp16.h>
#include <math.h>
#include <stdint.h>

// ---------------- problem constants ----------------
#define B_    32
#define S_    512
#define D_    512
#define NROWS (B_ * S_)      // 16384
#define H_    4
#define HD_   128
#define DFF   2048
#define NQ    8
#define NL    4
#define QKVLD 1536

// ---------------- scratch ----------------
__device__ __half g_xh  [NROWS * D_];
__device__ __half g_wih [3 * D_ * D_];
__device__ __half g_woh [D_ * D_];
__device__ __half g_w1h [DFF * D_];
__device__ __half g_w2h [D_ * DFF];
__device__ __half g_qkvh[NROWS * 3 * D_];
__device__ __half g_hbuf[NROWS * DFF];       // fp16 h (FFN intermediate)
__device__ __half g_attnh[NROWS * D_];
__device__ float  g_proj[NROWS * D_];
__device__ float  g_x1  [NROWS * D_];
__device__ float  g_x2  [NROWS * D_];
__device__ __half g_x2h [NROWS * D_];
__device__ float  g_ffn [NROWS * D_];
__device__ float  g_ang [NROWS * NQ];
__device__ float  g_z   [NROWS * NQ];

// ---------------- asm helpers ----------------
__device__ __forceinline__ void cp16(uint32_t dst, const void* src) {
    asm volatile("cp.async.cg.shared.global [%0], [%1], 16;" :: "r"(dst), "l"(src));
}
__device__ __forceinline__ void cp_commit() { asm volatile("cp.async.commit_group;"); }
template<int N> __device__ __forceinline__ void cp_wait() {
    asm volatile("cp.async.wait_group %0;" :: "n"(N));
}
__device__ __forceinline__ void ldm_x4(uint32_t (&r)[4], uint32_t addr) {
    asm volatile("ldmatrix.sync.aligned.m8n8.x4.shared.b16 {%0,%1,%2,%3}, [%4];"
                 : "=r"(r[0]), "=r"(r[1]), "=r"(r[2]), "=r"(r[3]) : "r"(addr));
}
__device__ __forceinline__ void ldm_x4_t(uint32_t (&r)[4], uint32_t addr) {
    asm volatile("ldmatrix.sync.aligned.m8n8.x4.trans.shared.b16 {%0,%1,%2,%3}, [%4];"
                 : "=r"(r[0]), "=r"(r[1]), "=r"(r[2]), "=r"(r[3]) : "r"(addr));
}
__device__ __forceinline__ void mma_f16(float (&c)[4], const uint32_t (&a)[4],
                                        uint32_t b0, uint32_t b1) {
    asm volatile(
        "mma.sync.aligned.m16n8k16.row.col.f32.f16.f16.f32 "
        "{%0,%1,%2,%3}, {%4,%5,%6,%7}, {%8,%9}, {%0,%1,%2,%3};"
        : "+f"(c[0]), "+f"(c[1]), "+f"(c[2]), "+f"(c[3])
        : "r"(a[0]), "r"(a[1]), "r"(a[2]), "r"(a[3]), "r"(b0), "r"(b1));
}
__device__ __forceinline__ uint32_t pack_h2(float lo, float hi) {
    __half2 h = __floats2half2_rn(lo, hi);
    return *reinterpret_cast<uint32_t*>(&h);
}

// =================== wide FP16 GEMM: 128x256 tile, 8 warps of 64x64 ===================
// C[M,N] = A[M,K](f16,row) * B[N,K](f16,row)^T + bias (+gelu). BK=16 double-buffered.
#define GSH 24
template<int EPI, int HOUT>  // EPI 1:+bias 2:+bias,gelu ; HOUT 0:f32 1:f16
__global__ void __launch_bounds__(256)
gemm_w(const __half* __restrict__ A, const __half* __restrict__ B,
       void* __restrict__ Cv, int N, int K, const float* __restrict__ bias) {
    __shared__ __half As[2][128 * GSH];
    __shared__ __half Bs[2][256 * GSH];

    const __half* Ab = A + (size_t)blockIdx.y * 128 * K;
    const __half* Bb = B + (size_t)blockIdx.x * 256 * K;

    const int tid = threadIdx.x;
    const int lane = tid & 31, wid = tid >> 5;
    const int warp_m = wid & 1, warp_n = wid >> 1;
    const int mbase = warp_m * 64, nbase = warp_n * 64;

    const uint32_t sA = (uint32_t)__cvta_generic_to_shared(&As[0][0]);
    const uint32_t sB = (uint32_t)__cvta_generic_to_shared(&Bs[0][0]);
    const uint32_t aStep = 128 * GSH * 2, bStep = 256 * GSH * 2;

    // cp.async mapping
    const int carow = tid >> 1, cacol = (tid & 1) * 8;   // A: 1 cp16
    const uint32_t adst = (uint32_t)(carow * GSH + cacol) * 2;
    const uint32_t bdst = (uint32_t)(tid * GSH) * 2;     // B: row tid, 2 cp16

    // ldmatrix coords
    const int arow = mbase + (lane & 15);
    const int acol = 8 * (lane >> 4);
    const int brow = nbase + (lane & 7) + 8 * ((lane >> 4) & 1);
    const int bcol = 8 * ((lane >> 3) & 1);

    float acc[4][8][4] = {};
    const int KT = K / 16;

    {
        cp16(sA + adst, Ab + (size_t)carow * K + cacol);
        cp16(sB + bdst, Bb + (size_t)tid * K);
        cp16(sB + bdst + 16, Bb + (size_t)tid * K + 8);
        cp_commit();
    }
    for (int kt = 0; kt < KT; kt++) {
        if (kt + 1 < KT) {
            const int nb = (kt + 1) & 1;
            const int kof = (kt + 1) * 16;
            cp16(sA + nb * aStep + adst, Ab + (size_t)carow * K + kof + cacol);
            cp16(sB + nb * bStep + bdst, Bb + (size_t)tid * K + kof);
            cp16(sB + nb * bStep + bdst + 16, Bb + (size_t)tid * K + kof + 8);
            cp_commit();
            cp_wait<1>();
        } else {
            cp_wait<0>();
        }
        __syncthreads();
        const uint32_t aB = sA + (kt & 1) * aStep;
        const uint32_t bB = sB + (kt & 1) * bStep;
        uint32_t afr[4][4], bfr[4][4];
        #pragma unroll
        for (int mf = 0; mf < 4; mf++)
            ldm_x4(afr[mf], aB + (uint32_t)((arow + mf * 16) * GSH + acol) * 2);
        #pragma unroll
        for (int g = 0; g < 4; g++)
            ldm_x4(bfr[g], bB + (uint32_t)((brow + g * 16) * GSH + bcol) * 2);
        #pragma unroll
        for (int mf = 0; mf < 4; mf++)
            #pragma unroll
            for (int g = 0; g < 4; g++) {
                mma_f16(acc[mf][2 * g],     afr[mf], bfr[g][0], bfr[g][1]);
                mma_f16(acc[mf][2 * g + 1], afr[mf], bfr[g][2], bfr[g][3]);
            }
        __syncthreads();
    }

    const int gi = lane >> 2, ti = lane & 3;
    float* Cf = (float*)Cv;
    __half* Ch = (__half*)Cv;
    #pragma unroll
    for (int mf = 0; mf < 4; mf++) {
        const int row = blockIdx.y * 128 + mbase + mf * 16 + gi;
        #pragma unroll
        for (int nf = 0; nf < 8; nf++) {
            const int col = blockIdx.x * 256 + nbase + nf * 8 + ti * 2;
            float v0 = acc[mf][nf][0], v1 = acc[mf][nf][1];
            float v2 = acc[mf][nf][2], v3 = acc[mf][nf][3];
            const float b0 = bias[col], b1 = bias[col + 1];
            v0 += b0; v1 += b1; v2 += b0; v3 += b1;
            if (EPI == 2) {
                v0 = 0.5f * v0 * (1.0f + erff(v0 * 0.70710678118654752f));
                v1 = 0.5f * v1 * (1.0f + erff(v1 * 0.70710678118654752f));
                v2 = 0.5f * v2 * (1.0f + erff(v2 * 0.70710678118654752f));
                v3 = 0.5f * v3 * (1.0f + erff(v3 * 0.70710678118654752f));
            }
            if (HOUT) {
                *reinterpret_cast<__half2*>(Ch + (size_t)row * N + col) = __floats2half2_rn(v0, v1);
                *reinterpret_cast<__half2*>(Ch + (size_t)(row + 8) * N + col) = __floats2half2_rn(v2, v3);
            } else {
                *reinterpret_cast<float2*>(Cf + (size_t)row * N + col) = make_float2(v0, v1);
                *reinterpret_cast<float2*>(Cf + (size_t)(row + 8) * N + col) = make_float2(v2, v3);
            }
        }
    }
}

// =================== fused flash attention ===================
// grid: (4 q-tiles, 128 bh). block: 256 thr = 8 warps, warp w owns Q rows w*16..+16.
// KV streamed in 64-row chunks; online softmax; out = fp16 ctx in (B,S,H*HD) layout.
#define FSH 136
__global__ void __launch_bounds__(256)
fa_k(const __half* __restrict__ qkv, __half* __restrict__ octx) {
    __shared__ __half sK[64 * FSH];
    __shared__ __half sV[64 * FSH];

    const int bh = blockIdx.y, b = bh >> 2, h = bh & 3;
    const int qt = blockIdx.x;
    const int tid = threadIdx.x, lane = tid & 31, wid = tid >> 5;
    const int gi = lane >> 2, ti = lane & 3;
    const float alpha = 0.08838834764831845f;

    const __half* qbase = qkv + ((size_t)(b * S_ + qt * 128)) * QKVLD + h * HD_;
    const __half* kbase = qkv + (size_t)b * S_ * QKVLD + D_ + h * HD_;

    const uint32_t sKa = (uint32_t)__cvta_generic_to_shared(sK);
    const uint32_t sVa = (uint32_t)__cvta_generic_to_shared(sV);

    // ldmatrix coords
    const int qrow_l = (wid & 3) * 16 + (lane & 15);       // within 64-row stage
    const int qcol   = 8 * (lane >> 4);
    const int krow   = (lane & 7) + 8 * ((lane >> 4) & 1); // non-trans B
    const int kcol   = 8 * ((lane >> 3) & 1);
    const int vrow   = (lane & 7) + 8 * ((lane >> 3) & 1); // trans B
    const int vcol   = 8 * (lane >> 4);

    // ---- stage Q (two 64-row stages through sK), keep fragments in registers ----
    uint32_t qf[8][4];
    #pragma unroll
    for (int st = 0; st < 2; st++) {
        #pragma unroll
        for (int i = 0; i < 4; i++) {
            int cpi = tid + i * 256;
            int r = cpi >> 4, c8 = (cpi & 15) * 8;
            cp16(sKa + (uint32_t)(r * FSH + c8) * 2, qbase + (size_t)(st * 64 + r) * QKVLD + c8);
        }
        cp_commit();
        cp_wait<0>();
        __syncthreads();
        if ((wid >> 2) == st) {
            #pragma unroll
            for (int ks = 0; ks < 8; ks++)
                ldm_x4(qf[ks], sKa + (uint32_t)(qrow_l * FSH + ks * 16 + qcol) * 2);
        }
        __syncthreads();
    }

    float oacc[16][4] = {};
    float m0 = -1e30f, m1 = -1e30f, l0 = 0.0f, l1 = 0.0f;

    for (int c = 0; c < 8; c++) {
        // load K,V chunk (64 x 128 each)
        #pragma unroll
        for (int i = 0; i < 4; i++) {
            int cpi = tid + i * 256;
            int r = cpi >> 4, c8 = (cpi & 15) * 8;
            const __half* kp = kbase + (size_t)(c * 64 + r) * QKVLD + c8;
            cp16(sKa + (uint32_t)(r * FSH + c8) * 2, kp);
            cp16(sVa + (uint32_t)(r * FSH + c8) * 2, kp + D_);
        }
        cp_commit();
        cp_wait<0>();
        __syncthreads();

        // S = Q K^T  (16 x 64 per warp)
        float sacc[8][4] = {};
        #pragma unroll
        for (int ks = 0; ks < 8; ks++) {
            uint32_t bfr[4][4];
            #pragma unroll
            for (int g = 0; g < 4; g++)
                ldm_x4(bfr[g], sKa + (uint32_t)((g * 16 + krow) * FSH + ks * 16 + kcol) * 2);
            #pragma unroll
            for (int g = 0; g < 4; g++) {
                mma_f16(sacc[2 * g],     qf[ks], bfr[g][0], bfr[g][1]);
                mma_f16(sacc[2 * g + 1], qf[ks], bfr[g][2], bfr[g][3]);
            }
        }

        // online softmax (rows gi and gi+8)
        float cm0 = -1e30f, cm1 = -1e30f;
        #pragma unroll
        for (int nf = 0; nf < 8; nf++) {
            cm0 = fmaxf(cm0, fmaxf(sacc[nf][0], sacc[nf][1]));
            cm1 = fmaxf(cm1, fmaxf(sacc[nf][2], sacc[nf][3]));
        }
        cm0 = fmaxf(cm0, __shfl_xor_sync(0xffffffffu, cm0, 1));
        cm0 = fmaxf(cm0, __shfl_xor_sync(0xffffffffu, cm0, 2));
        cm1 = fmaxf(cm1, __shfl_xor_sync(0xffffffffu, cm1, 1));
        cm1 = fmaxf(cm1, __shfl_xor_sync(0xffffffffu, cm1, 2));
        float mn0 = fmaxf(m0, alpha * cm0);
        float mn1 = fmaxf(m1, alpha * cm1);
        float sc0 = __expf(m0 - mn0);
        float sc1 = __expf(m1 - mn1);

        uint32_t pf[4][4];
        float ls0 = 0.0f, ls1 = 0.0f;
        #pragma unroll
        for (int nf = 0; nf < 8; nf++) {
            float p0 = __expf(sacc[nf][0] * alpha - mn0);
            float p1 = __expf(sacc[nf][1] * alpha - mn0);
            float p2 = __expf(sacc[nf][2] * alpha - mn1);
            float p3 = __expf(sacc[nf][3] * alpha - mn1);
            ls0 += p0 + p1; ls1 += p2 + p3;
            const int kk = nf >> 1, half = nf & 1;
            pf[kk][2 * half]     = pack_h2(p0, p1);
            pf[kk][2 * half + 1] = pack_h2(p2, p3);
        }
        ls0 += __shfl_xor_sync(0xffffffffu, ls0, 1);
        ls0 += __shfl_xor_sync(0xffffffffu, ls0, 2);
        ls1 += __shfl_xor_sync(0xffffffffu, ls1, 1);
        ls1 += __shfl_xor_sync(0xffffffffu, ls1, 2);
        l0 = l0 * sc0 + ls0;
        l1 = l1 * sc1 + ls1;
        m0 = mn0; m1 = mn1;
        #pragma unroll
        for (int onf = 0; onf < 16; onf++) {
            oacc[onf][0] *= sc0; oacc[onf][1] *= sc0;
            oacc[onf][2] *= sc1; oacc[onf][3] *= sc1;
        }

        // O += P V   (k = 64 kv, n = 128 hd)
        #pragma unroll
        for (int kk = 0; kk < 4; kk++) {
            #pragma unroll
            for (int g = 0; g < 8; g++) {
                uint32_t vfr[4];
                ldm_x4_t(vfr, sVa + (uint32_t)((kk * 16 + vrow) * FSH + g * 16 + vcol) * 2);
                mma_f16(oacc[2 * g],     pf[kk], vfr[0], vfr[1]);
                mma_f16(oacc[2 * g + 1], pf[kk], vfr[2], vfr[3]);
            }
        }
        __syncthreads();
    }

    // write context fp16: octx[(b*512 + qt*128 + wrow)*512 + h*128 + col]
    const float inv0 = 1.0f / l0, inv1 = 1.0f / l1;
    const int row0 = b * S_ + qt * 128 + wid * 16 + gi;
    #pragma unroll
    for (int onf = 0; onf < 16; onf++) {
        const int col = h * HD_ + onf * 8 + ti * 2;
        *reinterpret_cast<__half2*>(octx + (size_t)row0 * D_ + col) =
            __floats2half2_rn(oacc[onf][0] * inv0, oacc[onf][1] * inv0);
        *reinterpret_cast<__half2*>(octx + (size_t)(row0 + 8) * D_ + col) =
            __floats2half2_rn(oacc[onf][2] * inv1, oacc[onf][3] * inv1);
    }
}

// ---------------- fp32 -> fp16 ----------------
__global__ void f2h_k(const float* __restrict__ in, __half* __restrict__ out, int n4) {
    int i = blockIdx.x * blockDim.x + threadIdx.x;
    if (i < n4) {
        float4 v = reinterpret_cast<const float4*>(in)[i];
        reinterpret_cast<__half2*>(out)[i * 2]     = __floats2half2_rn(v.x, v.y);
        reinterpret_cast<__half2*>(out)[i * 2 + 1] = __floats2half2_rn(v.z, v.w);
    }
}

// ---------------- reductions / norms ----------------
__device__ __forceinline__ float block_reduce_sum(float v, float* red) {
    const int t = threadIdx.x;
    red[t] = v;
    __syncthreads();
    for (int s = 128; s > 0; s >>= 1) {
        if (t < s) red[t] += red[t + s];
        __syncthreads();
    }
    float r = red[0];
    __syncthreads();
    return r;
}

__global__ void add_ln_k(const float* __restrict__ a, const float* __restrict__ b,
                         const float* __restrict__ g, const float* __restrict__ be,
                         float* __restrict__ out) {
    __shared__ float red[256];
    const size_t row = blockIdx.x;
    const int t = threadIdx.x;
    float v0 = a[row * 512 + t] + b[row * 512 + t];
    float v1 = a[row * 512 + t + 256] + b[row * 512 + t + 256];
    float mean = block_reduce_sum(v0 + v1, red) * (1.0f / 512.0f);
    float d0 = v0 - mean, d1 = v1 - mean;
    float rstd = rsqrtf(block_reduce_sum(d0 * d0 + d1 * d1, red) * (1.0f / 512.0f) + 1e-5f);
    out[row * 512 + t]       = d0 * rstd * g[t] + be[t];
    out[row * 512 + t + 256] = d1 * rstd * g[t + 256] + be[t + 256];
}

__global__ void ln3_qin_k(const float* __restrict__ x1, const float* __restrict__ g,
                          const float* __restrict__ be, const float* __restrict__ qw,
                          const float* __restrict__ qb, float* __restrict__ ang) {
    __shared__ float rowv[512];
    __shared__ float red[256];
    const size_t row = blockIdx.x;
    const float* p = x1 + row * 512;
    const int t = threadIdx.x;
    float v0 = p[t], v1 = p[t + 256];
    rowv[t] = v0;
    rowv[t + 256] = v1;
    float mean = block_reduce_sum(v0 + v1, red) * (1.0f / 512.0f);
    float d0 = v0 - mean, d1 = v1 - mean;
    float rstd = rsqrtf(block_reduce_sum(d0 * d0 + d1 * d1, red) * (1.0f / 512.0f) + 1e-5f);
    const int w = t >> 5, lane = t & 31;
    float dot = 0.0f;
    for (int k = lane; k < 512; k += 32) {
        float xn = (rowv[k] - mean) * rstd * g[k] + be[k];
        dot = fmaf(xn, qw[w * 512 + k], dot);
    }
    #pragma unroll
    for (int o = 16; o > 0; o >>= 1) dot += __shfl_xor_sync(0xffffffffu, dot, o);
    if (lane == 0) ang[row * 8 + w] = dot + qb[w];
}

// ---------------- 8-qubit statevector simulator ----------------
__device__ __forceinline__ void rx_gate(float2* s, int pos, float c, float sn, int lane) {
    const int stride = 1 << pos;
    for (int p = lane; p < 128; p += 32) {
        int i0 = ((p >> pos) << (pos + 1)) | (p & (stride - 1));
        int i1 = i0 | stride;
        float2 a = s[i0], b = s[i1];
        s[i0] = make_float2(c * a.x + sn * b.y, c * a.y - sn * b.x);
        s[i1] = make_float2(sn * a.y + c * b.x, -sn * a.x + c * b.y);
    }
}
__device__ __forceinline__ void rz_gate(float2* s, int pos, float c, float sn, int lane) {
    for (int i = lane; i < 256; i += 32) {
        float2 a = s[i];
        if (i & (1 << pos)) s[i] = make_float2(a.x * c - a.y * sn, a.y * c + a.x * sn);
        else                s[i] = make_float2(a.x * c + a.y * sn, a.y * c - a.x * sn);
    }
}
__device__ __forceinline__ void cnot_gate(float2* s, int pt, int lane) {
    for (int p = lane; p < 64; p += 32) {
        int lower = p & ((1 << pt) - 1);
        int upper = p >> pt;
        int base = (upper << (pt + 2)) | lower;
        int i2 = base | (2 << pt);
        int i3 = base | (3 << pt);
        float2 tmp = s[i2];
        s[i2] = s[i3];
        s[i3] = tmp;
    }
}
__global__ void quantum_k(const float* __restrict__ angles, const float* __restrict__ qw,
                          float* __restrict__ zout) {
    __shared__ float2 st[8][256];
    const int warp = threadIdx.x >> 5, lane = threadIdx.x & 31;
    const size_t row = (size_t)blockIdx.x * 8 + warp;
    float2* s = st[warp];
    for (int i = lane; i < 256; i += 32) s[i] = make_float2(0.0f, 0.0f);
    __syncwarp();
    if (lane == 0) s[0] = make_float2(1.0f, 0.0f);
    __syncwarp();
    for (int q = 0; q < 8; q++) {
        float th = 0.5f * angles[row * 8 + q];
        float sn, c;
        sincosf(th, &sn, &c);
        rx_gate(s, 7 - q, c, sn, lane);
        __syncwarp();
        rz_gate(s, 7 - q, c, sn, lane);
        __syncwarp();
    }
    for (int l = 0; l < NL; l++) {
        for (int q = 0; q < 8; q++) {
            float snx, cx;
            sincosf(0.5f * qw[l * 16 + q], &snx, &cx);
            rx_gate(s, 7 - q, cx, snx, lane);
            __syncwarp();
            float snz, cz;
            sincosf(0.5f * qw[l * 16 + 8 + q], &snz, &cz);
            rz_gate(s, 7 - q, cz, snz, lane);
            __syncwarp();
        }
        for (int ctrl = 0; ctrl < 7; ctrl++) {
            cnot_gate(s, 6 - ctrl, lane);
            __syncwarp();
        }
    }
    float acc[8] = {0, 0, 0, 0, 0, 0, 0, 0};
    for (int i = lane; i < 256; i += 32) {
        float2 a = s[i];
        float pr = a.x * a.x + a.y * a.y;
        #pragma unroll
        for (int q = 0; q < 8; q++)
            acc[q] += (i & (1 << (7 - q))) ? -pr : pr;
    }
    #pragma unroll
    for (int q = 0; q < 8; q++)
        #pragma unroll
        for (int o = 16; o > 0; o >>= 1)
            acc[q] += __shfl_xor_sync(0xffffffffu, acc[q], o);
    if (lane == 0) {
        #pragma unroll
        for (int q = 0; q < 8; q++) zout[row * 8 + q] = acc[q];
    }
}

__global__ void qout_resid_h(const float* __restrict__ x1, const float* __restrict__ z,
                             const float* __restrict__ w, const float* __restrict__ bias,
                             float* __restrict__ x2, __half* __restrict__ x2h) {
    __shared__ float zs[8];
    const size_t row = blockIdx.x;
    if (threadIdx.x < 8) zs[threadIdx.x] = z[row * 8 + threadIdx.x];
    __syncthreads();
    for (int j = threadIdx.x; j < 512; j += 256) {
        const float* wj = w + j * 8;
        float acc = bias[j];
        #pragma unroll
        for (int q = 0; q < 8; q++) acc = fmaf(zs[q], wj[q], acc);
        float v = x1[row * 512 + j] + acc;
        x2[row * 512 + j] = v;
        x2h[row * 512 + j] = __float2half_rn(v);
    }
}

// ---------------- launch ----------------
extern "C" void kernel_launch(void* const* d_in, const int* in_sizes, int n_in,
                              void* d_out, int out_size) {
    const float* x          = (const float*)d_in[0];
    const float* attn_in_w  = (const float*)d_in[1];
    const float* attn_in_b  = (const float*)d_in[2];
    const float* attn_out_w = (const float*)d_in[3];
    const float* attn_out_b = (const float*)d_in[4];
    const float* ln1_g      = (const float*)d_in[5];
    const float* ln1_b      = (const float*)d_in[6];
    const float* ln2_g      = (const float*)d_in[7];
    const float* ln2_b      = (const float*)d_in[8];
    const float* ln3_g      = (const float*)d_in[9];
    const float* ln3_b      = (const float*)d_in[10];
    const float* qin_w      = (const float*)d_in[11];
    const float* qin_b      = (const float*)d_in[12];
    const float* qweights   = (const float*)d_in[13];
    const float* qout_w     = (const float*)d_in[14];
    const float* qout_b     = (const float*)d_in[15];
    const float* ffn_w1     = (const float*)d_in[16];
    const float* ffn_b1     = (const float*)d_in[17];
    const float* ffn_w2     = (const float*)d_in[18];
    const float* ffn_b2     = (const float*)d_in[19];
    float* out = (float*)d_out;

    __half *xh, *wih, *woh, *w1h, *w2h, *qkvh, *hbuf, *attnh, *x2h;
    float *proj, *x1, *x2, *ffn, *ang, *z;
    cudaGetSymbolAddress((void**)&xh,    g_xh);
    cudaGetSymbolAddress((void**)&wih,   g_wih);
    cudaGetSymbolAddress((void**)&woh,   g_woh);
    cudaGetSymbolAddress((void**)&w1h,   g_w1h);
    cudaGetSymbolAddress((void**)&w2h,   g_w2h);
    cudaGetSymbolAddress((void**)&qkvh,  g_qkvh);
    cudaGetSymbolAddress((void**)&hbuf,  g_hbuf);
    cudaGetSymbolAddress((void**)&attnh, g_attnh);
    cudaGetSymbolAddress((void**)&x2h,   g_x2h);
    cudaGetSymbolAddress((void**)&proj,  g_proj);
    cudaGetSymbolAddress((void**)&x1,    g_x1);
    cudaGetSymbolAddress((void**)&x2,    g_x2);
    cudaGetSymbolAddress((void**)&ffn,   g_ffn);
    cudaGetSymbolAddress((void**)&ang,   g_ang);
    cudaGetSymbolAddress((void**)&z,     g_z);

    const dim3 blk(256);

    // fp32 -> fp16 conversions
    f2h_k<<<(NROWS * D_ / 4 + 255) / 256, blk>>>(x, xh, NROWS * D_ / 4);
    f2h_k<<<(3 * D_ * D_ / 4 + 255) / 256, blk>>>(attn_in_w, wih, 3 * D_ * D_ / 4);
    f2h_k<<<(D_ * D_ / 4 + 255) / 256, blk>>>(attn_out_w, woh, D_ * D_ / 4);
    f2h_k<<<(DFF * D_ / 4 + 255) / 256, blk>>>(ffn_w1, w1h, DFF * D_ / 4);
    f2h_k<<<(D_ * DFF / 4 + 255) / 256, blk>>>(ffn_w2, w2h, D_ * DFF / 4);

    // QKV projection -> fp16
    gemm_w<1, 1><<<dim3(QKVLD / 256, NROWS / 128), blk>>>(xh, wih, qkvh, QKVLD, D_, attn_in_b);
    // fused attention -> fp16 context
    fa_k<<<dim3(4, B_ * H_), blk>>>(qkvh, attnh);
    // out projection -> fp32
    gemm_w<1, 0><<<dim3(D_ / 256, NROWS / 128), blk>>>(attnh, woh, proj, D_, D_, attn_out_b);
    // x1 = LN1(x + proj)
    add_ln_k<<<NROWS, blk>>>(x, proj, ln1_g, ln1_b, x1);
    // angles = LN3(x1) @ qin_w^T + qin_b
    ln3_qin_k<<<NROWS, blk>>>(x1, ln3_g, ln3_b, qin_w, qin_b, ang);
    // quantum expectation values
    quantum_k<<<NROWS / 8, blk>>>(ang, qweights, z);
    // x2 = x1 + z @ qout_w^T + qout_b
    qout_resid_h<<<NROWS, blk>>>(x1, z, qout_w, qout_b, x2, x2h);
    // FFN
    gemm_w<2, 1><<<dim3(DFF / 256, NROWS / 128), blk>>>(x2h, w1h, hbuf, DFF, D_, ffn_b1);
    gemm_w<1, 0><<<dim3(D_ / 256, NROWS / 128), blk>>>(hbuf, w2h, ffn, D_, DFF, ffn_b2);
    // out = LN2(x2 + ffn)
    add_ln_k<<<NROWS, blk>>>(x2, ffn, ln2_g, ln2_b, out);
}